// round 3
// baseline (speedup 1.0000x reference)
#include <cuda_runtime.h>
#include <cuda_bf16.h>
#include <cstdint>

// DomainGate: T=8192, E=16, C=512. Output (f32, packed):
//   [l_aux (1)] [combine1_sec T*E*C] [dispatch_mask T*E*C]  -> 134,217,729 floats.
// One-hot sparse result. Strategy:
//   1) pos_kernel: ballot-scan -> target[t] = dom[t]*C + slot, or -1 if dropped.
//   2) fill_kernel: single store-bound pass writing the ENTIRE output with
//      uint4 streaming stores; value computed inline (no memset, no scatter).
// E*C = 8192 floats/token -> token = j>>13, and a full warp shares one token
// (uniform target load).

#define NUM_EXPERTS 16
#define EC_SHIFT 13            // log2(E*C) = log2(8192)
#define EC_MASK  8191

// per-token packed target slot within [E*C): dom*C + p, or -1.
__device__ int g_target[1 << 15];

// One CTA, one warp per expert: stable rank of each kept token within its expert.
__global__ void __launch_bounds__(NUM_EXPERTS * 32, 1)
pos_kernel(const int* __restrict__ dom, const int* __restrict__ mask,
           int T, int capacity) {
    const int e    = threadIdx.x >> 5;
    const int lane = threadIdx.x & 31;

    int count = 0;
    for (int base = 0; base < T; base += 32) {
        const int t = base + lane;
        int d = -1;
        bool padded = true;
        if (t < T) {
            d = dom[t];
            padded = (mask[t] != 0);   // jax bool promoted to int32: nonzero = masked out
        }
        const bool match = (d == e) && !padded;
        const unsigned bal = __ballot_sync(0xffffffffu, match);
        const int p = count + __popc(bal & ((1u << lane) - 1u));
        if (t < T && d == e) {
            g_target[t] = (match && p < capacity) ? (e * capacity + p) : -1;
        }
        count += __popc(bal);
    }
}

// Per-element value of the packed output buffer.
__device__ __forceinline__ float out_val(long long i, long long TEC) {
    long long j = i - 1;               // skip l_aux
    if (j < 0) return 0.0f;            // l_aux = 0
    if (j >= TEC) j -= TEC;            // dispatch region == combine region content
    const int t     = (int)(j >> EC_SHIFT);
    const int inner = (int)j & EC_MASK;
    return (inner == g_target[t]) ? 1.0f : 0.0f;  // uniform load: warp shares t
}

// One pass over the whole output: 16B streaming stores.
__global__ void fill_kernel(float* __restrict__ out, long long n, long long TEC) {
    const long long chunk = (long long)blockIdx.x * blockDim.x + threadIdx.x;
    const long long i = chunk << 2;
    if (i >= n) return;
    if (i + 3 < n) {
        float4 v;
        v.x = out_val(i + 0, TEC);
        v.y = out_val(i + 1, TEC);
        v.z = out_val(i + 2, TEC);
        v.w = out_val(i + 3, TEC);
        __stcs(reinterpret_cast<float4*>(out + i), v);
    } else {
        for (long long k = i; k < n; k++)
            __stcs(out + k, out_val(k, TEC));
    }
}

extern "C" void kernel_launch(void* const* d_in, const int* in_sizes, int n_in,
                              void* d_out, int out_size) {
    // inputs: [0] input f32 [T,D] (unused), [1] domain_ids i32 [T], [2] mask (bool->i32) [T]
    const int* dom  = (const int*)d_in[1];
    const int* mask = (const int*)d_in[2];
    const int T = in_sizes[1];
    const int C = (T + NUM_EXPERTS - 1) / NUM_EXPERTS;
    const long long TEC = (long long)T * NUM_EXPERTS * C;
    const long long n   = (long long)out_size;

    float* out = (float*)d_out;

    // 1) positions (1 CTA, 16 warps, ~3us)
    pos_kernel<<<1, NUM_EXPERTS * 32>>>(dom, mask, T, C);

    // 2) single store-bound fill pass
    const long long chunks = (n + 3) >> 2;
    const int  threads = 256;
    const long long blocks = (chunks + threads - 1) / threads;
    fill_kernel<<<(unsigned)blocks, threads>>>(out, n, TEC);
}

// round 4
// speedup vs baseline: 1.3021x; 1.3021x over previous
#include <cuda_runtime.h>
#include <cuda_bf16.h>
#include <cstdint>

// DomainGate: T=8192, E=16, C=512. Output f32 packed:
//   [l_aux (1)] [combine1_sec T*E*C] [dispatch_mask T*E*C]  = 134,217,729 floats.
// One-hot sparse result (<= T ones). Strategy (R3):
//   1) zero_kernel: pure streaming STG.128 zero fill, ~1.4 instr per 16B
//      (R2 failed because inline value computation made it issue-bound at 84% alu).
//   2) pos_scatter_kernel: ONE CTA — ballot-scan ranks + scatter <= T ones
//      + tail element. Runs after the zero fill.

#define NUM_EXPERTS 16

// ---------------------------------------------------------------------------
// 1) Bulk zero: each CTA covers 2048 float4 (32KB); thread writes 8 float4
//    at stride 256 (warp-coalesced 4KB rows). Minimal per-thread math.
__global__ void __launch_bounds__(256, 8)
zero_kernel(float4* __restrict__ out, long long nvec) {
    const long long base = (long long)blockIdx.x * 2048 + threadIdx.x;
    const float4 z = make_float4(0.f, 0.f, 0.f, 0.f);
    if (base + 7 * 256 < nvec) {
        float4* p = out + base;
#pragma unroll
        for (int u = 0; u < 8; u++) __stcs(p + u * 256, z);
    } else {
#pragma unroll
        for (int u = 0; u < 8; u++) {
            const long long i = base + (long long)u * 256;
            if (i < nvec) __stcs(out + i, z);
        }
    }
}

// ---------------------------------------------------------------------------
// 2) One CTA: scan (warp e ranks tokens of expert e via ballots) + scatter.
__global__ void __launch_bounds__(512, 1)
pos_scatter_kernel(const int* __restrict__ dom, const int* __restrict__ mask,
                   int T, int capacity,
                   float* __restrict__ out, long long n, long long TEC) {
    __shared__ int s_target[8192];   // packed slot dom*C+p within [E*C), or -1

    const int tid  = threadIdx.x;
    const int warp = tid >> 5;
    const int lane = tid & 31;

    // Phase 0: tail element (bulk zero covered only (n>>2)*4 floats)
    if (tid == 0) {
        for (long long i = (n >> 2) << 2; i < n; i++) out[i] = 0.0f;
    }

    // Phase 1: scan. Warps 0..15 own experts 0..15; others idle.
    if (warp < NUM_EXPERTS) {
        const int e = warp;
        int count = 0;
        for (int basei = 0; basei < T; basei += 32) {
            const int t = basei + lane;
            int d = -1;
            bool padded = true;
            if (t < T) {
                d = dom[t];
                padded = (mask[t] != 0);  // jax bool promoted to int32
            }
            const bool match = (d == e) && !padded;
            const unsigned bal = __ballot_sync(0xffffffffu, match);
            const int p = count + __popc(bal & ((1u << lane) - 1u));
            if (t < T && d == e)
                s_target[t] = (match && p < capacity) ? (e * capacity + p) : -1;
            count += __popc(bal);
        }
    }
    __syncthreads();

    // Phase 2: scatter <= T ones into both regions.
    float* combine  = out + 1;
    float* dispatch = out + 1 + TEC;
    const long long EC = (long long)NUM_EXPERTS * capacity;
    for (int t = tid; t < T; t += blockDim.x) {
        const int tgt = s_target[t];
        if (tgt >= 0) {
            const long long off = (long long)t * EC + tgt;
            combine[off]  = 1.0f;
            dispatch[off] = 1.0f;
        }
    }
}

// ---------------------------------------------------------------------------
extern "C" void kernel_launch(void* const* d_in, const int* in_sizes, int n_in,
                              void* d_out, int out_size) {
    // inputs: [0] input f32 [T,D] (unused), [1] domain_ids i32 [T], [2] mask (bool->i32) [T]
    const int* dom  = (const int*)d_in[1];
    const int* mask = (const int*)d_in[2];
    const int T = in_sizes[1];
    const int C = (T + NUM_EXPERTS - 1) / NUM_EXPERTS;
    const long long TEC = (long long)T * NUM_EXPERTS * C;
    const long long n   = (long long)out_size;

    float* out = (float*)d_out;

    // 1) bulk zero fill: floor(n/4) float4 chunks
    const long long nvec   = n >> 2;
    const long long blocks = (nvec + 2047) / 2048;
    zero_kernel<<<(unsigned)blocks, 256>>>((float4*)out, nvec);

    // 2) scan + scatter (1 CTA)
    pos_scatter_kernel<<<1, 512>>>(dom, mask, T, C, out, n, TEC);
}

// round 5
// speedup vs baseline: 1.3942x; 1.0707x over previous
#include <cuda_runtime.h>
#include <cuda_bf16.h>
#include <cstdint>

// DomainGate: T=8192, E=16, C=512. Output f32 packed:
//   [l_aux (1)] [combine1_sec T*E*C] [dispatch_mask T*E*C] = 134,217,729 floats.
// One-hot sparse result (<= T ones).
//   1) zero_kernel: streaming STG.128 zero fill (measured ~52us) - unchanged.
//   2) pos_scatter_kernel (1 CTA): stage dom/mask in SMEM -> ballot scan from
//      SMEM (kills the 58us global-latency chain of R3) -> scatter ones + tail.

#define NUM_EXPERTS 16

// per-token packed slot dom*C+p within [E*C), or -1. Written+read inside one CTA.
__device__ int g_target[1 << 15];

// ---------------------------------------------------------------------------
// 1) Bulk zero: each CTA covers 2048 float4 (32KB); thread writes 8 float4
//    at stride 256 (warp-coalesced 4KB rows).
__global__ void __launch_bounds__(256, 8)
zero_kernel(float4* __restrict__ out, long long nvec) {
    const long long base = (long long)blockIdx.x * 2048 + threadIdx.x;
    const float4 z = make_float4(0.f, 0.f, 0.f, 0.f);
    if (base + 7 * 256 < nvec) {
        float4* p = out + base;
#pragma unroll
        for (int u = 0; u < 8; u++) __stcs(p + u * 256, z);
    } else {
#pragma unroll
        for (int u = 0; u < 8; u++) {
            const long long i = base + (long long)u * 256;
            if (i < nvec) __stcs(out + i, z);
        }
    }
}

// ---------------------------------------------------------------------------
// 2) One CTA, 512 threads = 16 warps (one per expert).
__global__ void __launch_bounds__(512, 1)
pos_scatter_kernel(const int* __restrict__ dom, const int* __restrict__ mask,
                   int T, int capacity,
                   float* __restrict__ out, long long n, long long TEC) {
    __shared__ int s_val[8192];   // dom | (padded << 8)

    const int tid  = threadIdx.x;
    const int warp = tid >> 5;
    const int lane = tid & 31;

    // Phase A: stage inputs with wide parallel loads (full MLP).
    {
        const int4* dom4  = (const int4*)dom;
        const int4* msk4  = (const int4*)mask;
        const int nv = T >> 2;             // 2048 int4 per array
        for (int i = tid; i < nv; i += 512) {
            const int4 d = dom4[i];
            const int4 m = msk4[i];
            const int b = i << 2;
            s_val[b + 0] = d.x | ((m.x != 0) << 8);
            s_val[b + 1] = d.y | ((m.y != 0) << 8);
            s_val[b + 2] = d.z | ((m.z != 0) << 8);
            s_val[b + 3] = d.w | ((m.w != 0) << 8);
        }
    }
    __syncthreads();

    // Phase B: ballot scan from SMEM. Warp e ranks kept tokens of expert e.
    {
        const int e = warp;
        const unsigned lt = (1u << lane) - 1u;
        int count = 0;
#pragma unroll 4
        for (int basei = 0; basei < T; basei += 32) {
            const int t = basei + lane;
            const int v = s_val[t];                  // conflict-free LDS
            const bool match = (v == e);             // implies !padded
            const unsigned bal = __ballot_sync(0xffffffffu, match);
            const int p = count + __popc(bal & lt);
            if ((v & 0xFF) == e)                     // exactly one owner warp
                g_target[t] = (match && p < capacity) ? (e * capacity + p) : -1;
            count += __popc(bal);
        }
    }
    __syncthreads();   // orders g_target global writes within the CTA

    // Phase C: scatter <= T ones into both regions; handle the tail float.
    float* combine  = out + 1;
    float* dispatch = out + 1 + TEC;
    const long long EC = (long long)NUM_EXPERTS * capacity;
    for (int t = tid; t < T; t += 512) {
        if (t == T - 1) out[n - 1] = 0.0f;   // tail not covered by vec4 zero fill;
                                             // same thread may overwrite with 1 below
        const int tgt = g_target[t];
        if (tgt >= 0) {
            const long long off = (long long)t * EC + tgt;
            combine[off]  = 1.0f;
            dispatch[off] = 1.0f;
        }
    }
}

// ---------------------------------------------------------------------------
extern "C" void kernel_launch(void* const* d_in, const int* in_sizes, int n_in,
                              void* d_out, int out_size) {
    // inputs: [0] input f32 [T,D] (unused), [1] domain_ids i32 [T], [2] mask (bool->i32) [T]
    const int* dom  = (const int*)d_in[1];
    const int* mask = (const int*)d_in[2];
    const int T = in_sizes[1];
    const int C = (T + NUM_EXPERTS - 1) / NUM_EXPERTS;
    const long long TEC = (long long)T * NUM_EXPERTS * C;
    const long long n   = (long long)out_size;

    float* out = (float*)d_out;

    // 1) bulk zero fill: floor(n/4) float4 chunks
    const long long nvec   = n >> 2;
    const long long blocks = (nvec + 2047) / 2048;
    zero_kernel<<<(unsigned)blocks, 256>>>((float4*)out, nvec);

    // 2) scan + scatter (1 CTA, SMEM-staged)
    pos_scatter_kernel<<<1, 512>>>(dom, mask, T, C, out, n, TEC);
}

// round 6
// speedup vs baseline: 1.5548x; 1.1152x over previous
#include <cuda_runtime.h>
#include <cuda_bf16.h>
#include <cstdint>

// DomainGate: T=8192, E=16, C=512. Output f32 packed:
//   [l_aux (1)] [combine T*E*C] [dispatch T*E*C] = 134,217,729 floats.
// R5: kill the single-SM scatter (35us of R4) by fusing the ones into the
// fill kernel. Each fill CTA covers 8192 floats = exactly one token span
// (offset by the l_aux float), so at most 2 one-positions per CTA, resolved
// with <= 2 uniform loads by thread 0 after a barrier.
//   kernel 1: scan_kernel (1 CTA) -> g_target[t] = dom*C + rank, or -1.
//   kernel 2: fill_kernel (16384 CTAs) -> zero 32KB + patch ones. No races.

#define NUM_EXPERTS 16

// per-token packed slot dom*C+p within [E*C), or -1.
__device__ int g_target[1 << 15];

// ---------------------------------------------------------------------------
// 1) Scan only: stage dom/mask in SMEM, ballot-rank per expert warp.
__global__ void __launch_bounds__(512, 1)
scan_kernel(const int* __restrict__ dom, const int* __restrict__ mask,
            int T, int capacity) {
    __shared__ int s_val[8192];   // dom | (padded << 8)

    const int tid  = threadIdx.x;
    const int warp = tid >> 5;
    const int lane = tid & 31;

    // stage inputs with wide parallel loads (full MLP)
    const int4* dom4 = (const int4*)dom;
    const int4* msk4 = (const int4*)mask;
    const int nv = T >> 2;
    for (int i = tid; i < nv; i += 512) {
        const int4 d = dom4[i];
        const int4 m = msk4[i];
        const int b = i << 2;
        s_val[b + 0] = d.x | ((m.x != 0) << 8);
        s_val[b + 1] = d.y | ((m.y != 0) << 8);
        s_val[b + 2] = d.z | ((m.z != 0) << 8);
        s_val[b + 3] = d.w | ((m.w != 0) << 8);
    }
    __syncthreads();

    // warp e ranks kept tokens of expert e
    const int e = warp;
    const unsigned lt = (1u << lane) - 1u;
    int count = 0;
#pragma unroll 4
    for (int basei = 0; basei < T; basei += 32) {
        const int t = basei + lane;
        const int v = s_val[t];                  // conflict-free LDS
        const bool match = (v == e);             // implies !padded
        const unsigned bal = __ballot_sync(0xffffffffu, match);
        const int p = count + __popc(bal & lt);
        if ((v & 0xFF) == e)                     // exactly one owner warp
            g_target[t] = (match && p < capacity) ? (e * capacity + p) : -1;
        count += __popc(bal);
    }
}

// ---------------------------------------------------------------------------
// 2) Fused zero + one-patch. CTA b covers floats [b*8192, (b+1)*8192).
//    Grid is exactly nvec/2048 CTAs (nvec = 33,554,432 -> 16384 CTAs).
__global__ void __launch_bounds__(256, 8)
fill_kernel(float* __restrict__ out, long long nvec, long long n, int nblocks) {
    const int b = blockIdx.x;
    const long long vbase = (long long)b * 2048 + threadIdx.x;
    const float4 z = make_float4(0.f, 0.f, 0.f, 0.f);
    float4* o4 = (float4*)out;
    if (vbase + 7 * 256 < nvec) {
        float4* p = o4 + vbase;
#pragma unroll
        for (int u = 0; u < 8; u++) __stcs(p + u * 256, z);
    } else {
#pragma unroll
        for (int u = 0; u < 8; u++) {
            const long long i = vbase + (long long)u * 256;
            if (i < nvec) __stcs(o4 + i, z);
        }
    }
    __syncthreads();   // block-scope fence: zero stores ordered before patches

    if (threadIdx.x == 0) {
        const long long base = (long long)b << 13;   // first float of this CTA
        // candidate A: token owning [base+1, base+8191]
        const int tA = (b < 8192) ? b : (b - 8192);
        if (tA < 8192) {
            const int tgtA = g_target[tA];
            if (tgtA >= 0 && tgtA <= 8190) out[base + 1 + tgtA] = 1.0f;
        }
        // candidate B: boundary float at `base` = previous token's tgt==8191
        if (b > 0) {
            const int tB = (b == 8192) ? 8191 : (tA - 1);
            if (tB >= 0 && g_target[tB] == 8191) out[base] = 1.0f;
        }
        // tail float (index n-1 = dispatch token 8191, tgt 8191), uncovered by vec4s
        if (b == nblocks - 1)
            out[n - 1] = (g_target[8191] == 8191) ? 1.0f : 0.0f;
    }
}

// ---------------------------------------------------------------------------
extern "C" void kernel_launch(void* const* d_in, const int* in_sizes, int n_in,
                              void* d_out, int out_size) {
    // inputs: [0] input f32 [T,D] (unused), [1] domain_ids i32 [T], [2] mask (bool->i32) [T]
    const int* dom  = (const int*)d_in[1];
    const int* mask = (const int*)d_in[2];
    const int T = in_sizes[1];
    const int C = (T + NUM_EXPERTS - 1) / NUM_EXPERTS;
    const long long n = (long long)out_size;

    float* out = (float*)d_out;

    // 1) scan (1 CTA, SMEM-staged ballots)
    scan_kernel<<<1, 512>>>(dom, mask, T, C);

    // 2) fused zero + patch
    const long long nvec   = n >> 2;
    const int blocks = (int)((nvec + 2047) / 2048);
    fill_kernel<<<blocks, 256>>>(out, nvec, n, blocks);
}

// round 7
// speedup vs baseline: 1.5597x; 1.0031x over previous
#include <cuda_runtime.h>
#include <cuda_bf16.h>
#include <cstdint>

// DomainGate: T=8192, E=16, C=512. Output f32 packed:
//   [l_aux (1)] [combine T*E*C] [dispatch T*E*C] = 134,217,729 floats.
// R6 strategy (92.5us) + PDL overlap:
//   scan_kernel (1 CTA)  -> g_target[t] = dom*C + rank, or -1.
//   fill_kernel (16384 CTAs, launched with ProgrammaticStreamSerialization):
//     zero 32KB/CTA (runs CONCURRENTLY with scan) -> cudaGridDependencySynchronize
//     -> patch <= 2 one-positions per CTA. No cross-CTA races.

#define NUM_EXPERTS 16

// per-token packed slot dom*C+p within [E*C), or -1.
__device__ int g_target[1 << 15];

// ---------------------------------------------------------------------------
// 1) Scan: stage dom/mask in SMEM, ballot-rank per expert warp.
__global__ void __launch_bounds__(512, 1)
scan_kernel(const int* __restrict__ dom, const int* __restrict__ mask,
            int T, int capacity) {
    __shared__ int s_val[8192];   // dom | (padded << 8)

    const int tid  = threadIdx.x;
    const int warp = tid >> 5;
    const int lane = tid & 31;

    // stage inputs with wide parallel loads (full MLP)
    const int4* dom4 = (const int4*)dom;
    const int4* msk4 = (const int4*)mask;
    const int nv = T >> 2;
    for (int i = tid; i < nv; i += 512) {
        const int4 d = dom4[i];
        const int4 m = msk4[i];
        const int b = i << 2;
        s_val[b + 0] = d.x | ((m.x != 0) << 8);
        s_val[b + 1] = d.y | ((m.y != 0) << 8);
        s_val[b + 2] = d.z | ((m.z != 0) << 8);
        s_val[b + 3] = d.w | ((m.w != 0) << 8);
    }
    __syncthreads();

    // warp e ranks kept tokens of expert e
    const int e = warp;
    const unsigned lt = (1u << lane) - 1u;
    int count = 0;
#pragma unroll 4
    for (int basei = 0; basei < T; basei += 32) {
        const int t = basei + lane;
        const int v = s_val[t];                  // conflict-free LDS
        const bool match = (v == e);             // implies !padded
        const unsigned bal = __ballot_sync(0xffffffffu, match);
        const int p = count + __popc(bal & lt);
        if ((v & 0xFF) == e)                     // exactly one owner warp
            g_target[t] = (match && p < capacity) ? (e * capacity + p) : -1;
        count += __popc(bal);
    }
}

// ---------------------------------------------------------------------------
// 2) Fused zero + one-patch. CTA b covers floats [b*8192, (b+1)*8192).
//    Launched with PDL: zero phase overlaps scan_kernel; the patch waits on it.
__global__ void __launch_bounds__(256, 8)
fill_kernel(float* __restrict__ out, long long nvec, long long n, int nblocks) {
    const int b = blockIdx.x;
    const long long vbase = (long long)b * 2048 + threadIdx.x;
    const float4 z = make_float4(0.f, 0.f, 0.f, 0.f);
    float4* o4 = (float4*)out;
    if (vbase + 7 * 256 < nvec) {
        float4* p = o4 + vbase;
#pragma unroll
        for (int u = 0; u < 8; u++) __stcs(p + u * 256, z);
    } else {
#pragma unroll
        for (int u = 0; u < 8; u++) {
            const long long i = vbase + (long long)u * 256;
            if (i < nvec) __stcs(o4 + i, z);
        }
    }
    __syncthreads();   // zero stores of this CTA ordered before the patch

    if (threadIdx.x == 0) {
        cudaGridDependencySynchronize();   // wait for scan_kernel's g_target

        const long long base = (long long)b << 13;   // first float of this CTA
        // candidate A: token owning [base+1, base+8191]
        const int tA = (b < 8192) ? b : (b - 8192);
        if (tA < 8192) {
            const int tgtA = g_target[tA];
            if (tgtA >= 0 && tgtA <= 8190) out[base + 1 + tgtA] = 1.0f;
        }
        // candidate B: boundary float at `base` = previous token's tgt==8191
        if (b > 0) {
            const int tB = (b == 8192) ? 8191 : (tA - 1);
            if (tB >= 0 && g_target[tB] == 8191) out[base] = 1.0f;
        }
        // tail float (index n-1 = dispatch token 8191, tgt 8191), uncovered by vec4s
        if (b == nblocks - 1)
            out[n - 1] = (g_target[8191] == 8191) ? 1.0f : 0.0f;
    }
}

// ---------------------------------------------------------------------------
extern "C" void kernel_launch(void* const* d_in, const int* in_sizes, int n_in,
                              void* d_out, int out_size) {
    // inputs: [0] input f32 [T,D] (unused), [1] domain_ids i32 [T], [2] mask (bool->i32) [T]
    const int* dom  = (const int*)d_in[1];
    const int* mask = (const int*)d_in[2];
    const int T = in_sizes[1];
    const int C = (T + NUM_EXPERTS - 1) / NUM_EXPERTS;
    const long long n = (long long)out_size;

    float* out = (float*)d_out;

    // 1) scan (1 CTA) — launched first, resident before fill starts
    scan_kernel<<<1, 512>>>(dom, mask, T, C);

    // 2) fill with Programmatic Dependent Launch: zero phase overlaps the scan
    const long long nvec = n >> 2;
    const int blocks = (int)((nvec + 2047) / 2048);

    cudaLaunchConfig_t cfg = {};
    cfg.gridDim  = dim3((unsigned)blocks, 1, 1);
    cfg.blockDim = dim3(256, 1, 1);
    cfg.dynamicSmemBytes = 0;
    cfg.stream = 0;
    cudaLaunchAttribute attr[1];
    attr[0].id = cudaLaunchAttributeProgrammaticStreamSerialization;
    attr[0].val.programmaticStreamSerializationAllowed = 1;
    cfg.attrs = attr;
    cfg.numAttrs = 1;
    cudaLaunchKernelEx(&cfg, fill_kernel, out, nvec, n, blocks);
}

// round 8
// speedup vs baseline: 1.5951x; 1.0227x over previous
#include <cuda_runtime.h>
#include <cuda_bf16.h>
#include <cstdint>

// DomainGate: T=8192, E=16, C=512. Output f32 packed:
//   [l_aux (1)] [combine T*E*C] [dispatch T*E*C] = 134,217,729 floats.
// R8 = R7 + the missing PDL trigger:
//   scan_kernel (1 CTA): cudaTriggerProgrammaticLaunchCompletion() FIRST, so
//     the fill grid launches immediately and its zero phase overlaps the scan.
//   fill_kernel (16384 CTAs, PSS attr): zero 32KB/CTA -> __syncthreads ->
//     cudaGridDependencySynchronize (waits for scan COMPLETION + visibility)
//     -> patch <= 2 one-positions per CTA. No cross-CTA races.

#define NUM_EXPERTS 16

// per-token packed slot dom*C+p within [E*C), or -1.
__device__ int g_target[1 << 15];

// ---------------------------------------------------------------------------
// 1) Scan: stage dom/mask in SMEM, ballot-rank per expert warp.
__global__ void __launch_bounds__(512, 1)
scan_kernel(const int* __restrict__ dom, const int* __restrict__ mask,
            int T, int capacity) {
    // Release the dependent fill grid NOW — its zero phase needs nothing from us.
    cudaTriggerProgrammaticLaunchCompletion();

    __shared__ int s_val[8192];   // dom | (padded << 8)

    const int tid  = threadIdx.x;
    const int warp = tid >> 5;
    const int lane = tid & 31;

    // stage inputs with wide parallel loads (full MLP)
    const int4* dom4 = (const int4*)dom;
    const int4* msk4 = (const int4*)mask;
    const int nv = T >> 2;
    for (int i = tid; i < nv; i += 512) {
        const int4 d = dom4[i];
        const int4 m = msk4[i];
        const int b = i << 2;
        s_val[b + 0] = d.x | ((m.x != 0) << 8);
        s_val[b + 1] = d.y | ((m.y != 0) << 8);
        s_val[b + 2] = d.z | ((m.z != 0) << 8);
        s_val[b + 3] = d.w | ((m.w != 0) << 8);
    }
    __syncthreads();

    // warp e ranks kept tokens of expert e
    const int e = warp;
    const unsigned lt = (1u << lane) - 1u;
    int count = 0;
#pragma unroll 4
    for (int basei = 0; basei < T; basei += 32) {
        const int t = basei + lane;
        const int v = s_val[t];                  // conflict-free LDS
        const bool match = (v == e);             // implies !padded
        const unsigned bal = __ballot_sync(0xffffffffu, match);
        const int p = count + __popc(bal & lt);
        if ((v & 0xFF) == e)                     // exactly one owner warp
            g_target[t] = (match && p < capacity) ? (e * capacity + p) : -1;
        count += __popc(bal);
    }
}

// ---------------------------------------------------------------------------
// 2) Fused zero + one-patch. CTA b covers floats [b*8192, (b+1)*8192).
//    Zero phase overlaps scan_kernel; patch waits on its completion.
__global__ void __launch_bounds__(256, 8)
fill_kernel(float* __restrict__ out, long long nvec, long long n, int nblocks) {
    const int b = blockIdx.x;
    const long long vbase = (long long)b * 2048 + threadIdx.x;
    const float4 z = make_float4(0.f, 0.f, 0.f, 0.f);
    float4* o4 = (float4*)out;
    if (vbase + 7 * 256 < nvec) {
        float4* p = o4 + vbase;
#pragma unroll
        for (int u = 0; u < 8; u++) __stcs(p + u * 256, z);
    } else {
#pragma unroll
        for (int u = 0; u < 8; u++) {
            const long long i = vbase + (long long)u * 256;
            if (i < nvec) __stcs(o4 + i, z);
        }
    }
    __syncthreads();   // zero stores of this CTA ordered before the patch

    if (threadIdx.x == 0) {
        cudaGridDependencySynchronize();   // wait for scan_kernel's g_target

        const long long base = (long long)b << 13;   // first float of this CTA
        // candidate A: token owning [base+1, base+8191]
        const int tA = (b < 8192) ? b : (b - 8192);
        if (tA < 8192) {
            const int tgtA = g_target[tA];
            if (tgtA >= 0 && tgtA <= 8190) out[base + 1 + tgtA] = 1.0f;
        }
        // candidate B: boundary float at `base` = previous token's tgt==8191
        if (b > 0) {
            const int tB = (b == 8192) ? 8191 : (tA - 1);
            if (tB >= 0 && g_target[tB] == 8191) out[base] = 1.0f;
        }
        // tail float (index n-1 = dispatch token 8191, tgt 8191), uncovered by vec4s
        if (b == nblocks - 1)
            out[n - 1] = (g_target[8191] == 8191) ? 1.0f : 0.0f;
    }
}

// ---------------------------------------------------------------------------
extern "C" void kernel_launch(void* const* d_in, const int* in_sizes, int n_in,
                              void* d_out, int out_size) {
    // inputs: [0] input f32 [T,D] (unused), [1] domain_ids i32 [T], [2] mask (bool->i32) [T]
    const int* dom  = (const int*)d_in[1];
    const int* mask = (const int*)d_in[2];
    const int T = in_sizes[1];
    const int C = (T + NUM_EXPERTS - 1) / NUM_EXPERTS;
    const long long n = (long long)out_size;

    float* out = (float*)d_out;

    // 1) scan (1 CTA) — triggers programmatic completion immediately
    scan_kernel<<<1, 512>>>(dom, mask, T, C);

    // 2) fill with Programmatic Dependent Launch: zero phase overlaps the scan
    const long long nvec = n >> 2;
    const int blocks = (int)((nvec + 2047) / 2048);

    cudaLaunchConfig_t cfg = {};
    cfg.gridDim  = dim3((unsigned)blocks, 1, 1);
    cfg.blockDim = dim3(256, 1, 1);
    cfg.dynamicSmemBytes = 0;
    cfg.stream = 0;
    cudaLaunchAttribute attr[1];
    attr[0].id = cudaLaunchAttributeProgrammaticStreamSerialization;
    attr[0].val.programmaticStreamSerializationAllowed = 1;
    cfg.attrs = attr;
    cfg.numAttrs = 1;
    cudaLaunchKernelEx(&cfg, fill_kernel, out, nvec, n, blocks);
}